// round 4
// baseline (speedup 1.0000x reference)
#include <cuda_runtime.h>
#include <cstdint>
#include <cstddef>

#define N_ROWS   262144
#define DDIM     64
#define QSTAGES  8
#define KCODES   1024
#define TM       128
#define TN       128
#define NTHREADS 512
#define TPAD     132
#define CPAD     132

// shared memory layout (float units)
#define OFF_XT   0
#define OFF_QT   (OFF_XT + DDIM * TPAD)
#define OFF_RT   (OFF_QT + DDIM * TPAD)
#define OFF_CB   (OFF_RT + DDIM * TPAD)          // double-buffered codebook chunk
#define OFF_HN   (OFF_CB + 2 * DDIM * CPAD)
#define OFF_IDX  (OFF_HN + KCODES)               // TM ints
#define SMEM_FLOATS (OFF_IDX + TM)
#define SMEM_BYTES  (SMEM_FLOATS * 4)

// hn[q][k] = XLA-emulated fp32 sum(cb*cb) (warp-tree reduction, see hn_kernel)
__device__ float g_hn[QSTAGES * KCODES];

// ---------------- packed f32x2 helpers ----------------
__device__ __forceinline__ void ffma2(unsigned long long& acc,
                                      unsigned long long a,
                                      unsigned long long b) {
    asm("fma.rn.f32x2 %0, %1, %2, %0;" : "+l"(acc) : "l"(a), "l"(b));
}
__device__ __forceinline__ unsigned long long dup2(float v) {
    unsigned long long r;
    asm("mov.b64 %0, {%1, %1};" : "=l"(r) : "f"(v));
    return r;
}
__device__ __forceinline__ float2 unpack2(unsigned long long p) {
    float2 r;
    asm("mov.b64 {%0, %1}, %2;" : "=f"(r.x), "=f"(r.y) : "l"(p));
    return r;
}

// ---------------- codebook norms: emulate XLA row-reduction ----------------
__global__ void hn_kernel(const float* __restrict__ cb) {
    int warp = (blockIdx.x * blockDim.x + threadIdx.x) >> 5;
    int lane = threadIdx.x & 31;
    if (warp < QSTAGES * KCODES) {
        const float* row = cb + (size_t)warp * DDIM;
        float c0 = row[lane];
        float c1 = row[lane + 32];
        float acc = __fmaf_rn(c0, c0, 0.0f);
        acc = __fmaf_rn(c1, c1, acc);
#pragma unroll
        for (int off = 16; off > 0; off >>= 1) {
            float sh = __shfl_down_sync(0xffffffffu, acc, off);
            acc = acc + sh;
        }
        if (lane == 0) g_hn[warp] = acc;
    }
}

// ---------------- codebook chunk staging (512 threads) ----------------
__device__ __forceinline__ void load_chunk(const float* __restrict__ cbq, int c,
                                           int tid, float4* st) {
    int klocal = tid >> 2;            // 0..127
    int d0 = (tid & 3) << 4;          // 0,16,32,48
    const float4* p = reinterpret_cast<const float4*>(
        cbq + ((size_t)(c * TN + klocal)) * DDIM + d0);
#pragma unroll
    for (int j = 0; j < 4; j++) st[j] = p[j];
}
__device__ __forceinline__ void sts_chunk(float* __restrict__ buf, int tid,
                                          const float4* st) {
    int klocal = tid >> 2;
    int d0 = (tid & 3) << 4;
#pragma unroll
    for (int j = 0; j < 4; j++) {
        int dd = d0 + (j << 2);
        buf[(dd + 0) * CPAD + klocal] = st[j].x;
        buf[(dd + 1) * CPAD + klocal] = st[j].y;
        buf[(dd + 2) * CPAD + klocal] = st[j].z;
        buf[(dd + 3) * CPAD + klocal] = st[j].w;
    }
}

// ---------------- main fused RVQ kernel ----------------
__global__ void __launch_bounds__(NTHREADS, 1)
rvq_kernel(const float* __restrict__ x, const float* __restrict__ cb,
           float* __restrict__ qz, float* __restrict__ enc_f,
           int* __restrict__ enc_i) {
    extern __shared__ float smem[];
    float* s_xT  = smem + OFF_XT;
    float* s_qT  = smem + OFF_QT;
    float* s_rT  = smem + OFF_RT;
    float* s_cbT = smem + OFF_CB;
    float* s_hn  = smem + OFF_HN;
    int*   s_idx = reinterpret_cast<int*>(smem + OFF_IDX);

    const int tid = threadIdx.x;
    const int tx = tid & 15;          // 16 col-groups of 8
    const int ty = tid >> 4;          // 32 row-groups of 4
    const int row_base = blockIdx.x * TM;

    // ---- init: xT = x (transposed), qT = 0, rT = x ----
    {
        int n = tid >> 2;
        int d0 = (tid & 3) << 4;
        const float4* xp = reinterpret_cast<const float4*>(
            x + (size_t)(row_base + n) * DDIM + d0);
#pragma unroll
        for (int j = 0; j < 4; j++) {
            float4 v = xp[j];
            int dd = d0 + (j << 2);
            s_xT[(dd + 0) * TPAD + n] = v.x;
            s_xT[(dd + 1) * TPAD + n] = v.y;
            s_xT[(dd + 2) * TPAD + n] = v.z;
            s_xT[(dd + 3) * TPAD + n] = v.w;
            s_qT[(dd + 0) * TPAD + n] = 0.f;
            s_qT[(dd + 1) * TPAD + n] = 0.f;
            s_qT[(dd + 2) * TPAD + n] = 0.f;
            s_qT[(dd + 3) * TPAD + n] = 0.f;
            s_rT[(dd + 0) * TPAD + n] = v.x;
            s_rT[(dd + 1) * TPAD + n] = v.y;
            s_rT[(dd + 2) * TPAD + n] = v.z;
            s_rT[(dd + 3) * TPAD + n] = v.w;
        }
    }

    for (int q = 0; q < QSTAGES; q++) {
        const float* cbq = cb + (size_t)q * (KCODES * DDIM);

        for (int i = tid; i < KCODES; i += NTHREADS)
            s_hn[i] = g_hn[q * KCODES + i];
        __syncthreads();

        // prologue: chunk 0 -> buffer 0
        float4 st[4];
        load_chunk(cbq, 0, tid, st);
        sts_chunk(s_cbT + 0, tid, st);
        __syncthreads();

        // per-lane running argmin of d = fma(-2, s, hn)
        float bestd[4];
        int besti[4];
#pragma unroll
        for (int i = 0; i < 4; i++) { bestd[i] = 3.0e38f; besti[i] = 0x7fffffff; }

        for (int c = 0; c < KCODES / TN; c++) {
            if (c < KCODES / TN - 1) load_chunk(cbq, c + 1, tid, st);

            const float* bufb = s_cbT + (c & 1) * (DDIM * CPAD);

            unsigned long long acc[4][4];
#pragma unroll
            for (int i = 0; i < 4; i++)
#pragma unroll
                for (int j = 0; j < 4; j++) acc[i][j] = 0ULL;

            // s = sum_d r[d]*c[d], fma, d ascending, single accumulator per
            // output (per packed half) — bit-identical to SGEMM's k-loop.
#pragma unroll 4
            for (int d = 0; d < DDIM; d++) {
                float4 a0 = *reinterpret_cast<const float4*>(
                    s_rT + d * TPAD + (ty << 2));
                const ulonglong2* bp = reinterpret_cast<const ulonglong2*>(
                    bufb + d * CPAD + (tx << 3));
                ulonglong2 b0 = bp[0];
                ulonglong2 b1 = bp[1];
                float av[4] = {a0.x, a0.y, a0.z, a0.w};
#pragma unroll
                for (int i = 0; i < 4; i++) {
                    unsigned long long ad = dup2(av[i]);
                    ffma2(acc[i][0], ad, b0.x);
                    ffma2(acc[i][1], ad, b0.y);
                    ffma2(acc[i][2], ad, b1.x);
                    ffma2(acc[i][3], ad, b1.y);
                }
            }

            // epilogue: d = fma(-2, s, hn); running strict min
            {
                int colbase = c * TN + (tx << 3);
                float hnv[8];
                *reinterpret_cast<float4*>(hnv) =
                    *reinterpret_cast<const float4*>(s_hn + colbase);
                *reinterpret_cast<float4*>(hnv + 4) =
                    *reinterpret_cast<const float4*>(s_hn + colbase + 4);
#pragma unroll
                for (int i = 0; i < 4; i++) {
#pragma unroll
                    for (int j = 0; j < 4; j++) {
                        float2 v = unpack2(acc[i][j]);
                        int c0 = colbase + 2 * j;
                        float d0v = __fmaf_rn(-2.0f, v.x, hnv[2 * j]);
                        float d1v = __fmaf_rn(-2.0f, v.y, hnv[2 * j + 1]);
                        if (d0v < bestd[i]) { bestd[i] = d0v; besti[i] = c0; }
                        if (d1v < bestd[i]) { bestd[i] = d1v; besti[i] = c0 + 1; }
                    }
                }
            }

            if (c < KCODES / TN - 1) {
                sts_chunk(s_cbT + ((c + 1) & 1) * (DDIM * CPAD), tid, st);
                __syncthreads();
            }
        }

        // cross-lane argmin merge over 16 tx lanes (xor offsets stay inside
        // each 16-lane half-warp; (d, idx) lexicographic == first occurrence)
#pragma unroll
        for (int i = 0; i < 4; i++) {
#pragma unroll
            for (int off = 8; off > 0; off >>= 1) {
                float ov = __shfl_xor_sync(0xffffffffu, bestd[i], off);
                int oi = __shfl_xor_sync(0xffffffffu, besti[i], off);
                if (ov < bestd[i] || (ov == bestd[i] && oi < besti[i])) {
                    bestd[i] = ov;
                    besti[i] = oi;
                }
            }
        }
        if (tx == 0) {
#pragma unroll
            for (int i = 0; i < 4; i++) {
                int row = (ty << 2) + i;
                int id = besti[i];
                s_idx[row] = id;
                size_t e = (size_t)(row_base + row) * QSTAGES + q;
                if (enc_f) enc_f[e] = (float)id;
                if (enc_i) enc_i[e] = id;
            }
        }
        __syncthreads();

        // ---- update: q += cb[idx] (fp32, ref order); r = x - q ----
        {
            int n = tid >> 2;
            int d0 = (tid & 3) << 4;
            int id = s_idx[n];
            const float4* cp = reinterpret_cast<const float4*>(
                cbq + (size_t)id * DDIM + d0);
#pragma unroll
            for (int j = 0; j < 4; j++) {
                float4 v = cp[j];
                int dd = d0 + (j << 2);
                float qv0 = s_qT[(dd + 0) * TPAD + n] + v.x;
                float qv1 = s_qT[(dd + 1) * TPAD + n] + v.y;
                float qv2 = s_qT[(dd + 2) * TPAD + n] + v.z;
                float qv3 = s_qT[(dd + 3) * TPAD + n] + v.w;
                s_qT[(dd + 0) * TPAD + n] = qv0;
                s_qT[(dd + 1) * TPAD + n] = qv1;
                s_qT[(dd + 2) * TPAD + n] = qv2;
                s_qT[(dd + 3) * TPAD + n] = qv3;
                s_rT[(dd + 0) * TPAD + n] = s_xT[(dd + 0) * TPAD + n] - qv0;
                s_rT[(dd + 1) * TPAD + n] = s_xT[(dd + 1) * TPAD + n] - qv1;
                s_rT[(dd + 2) * TPAD + n] = s_xT[(dd + 2) * TPAD + n] - qv2;
                s_rT[(dd + 3) * TPAD + n] = s_xT[(dd + 3) * TPAD + n] - qv3;
            }
        }
        __syncthreads();
    }

    // ---- output quantized = qT (bit-exact accumulation) ----
    if (qz) {
        int n = tid >> 2;
        int d0 = (tid & 3) << 4;
        size_t base = (size_t)(row_base + n) * DDIM + d0;
#pragma unroll
        for (int j = 0; j < 4; j++) {
            int dd = d0 + (j << 2);
            float4 o;
            o.x = s_qT[(dd + 0) * TPAD + n];
            o.y = s_qT[(dd + 1) * TPAD + n];
            o.z = s_qT[(dd + 2) * TPAD + n];
            o.w = s_qT[(dd + 3) * TPAD + n];
            *reinterpret_cast<float4*>(qz + base + (j << 2)) = o;
        }
    }
}

// ---------------- launch ----------------
extern "C" void kernel_launch(void* const* d_in, const int* in_sizes, int n_in,
                              void* d_out, int out_size) {
    const float* x = (const float*)d_in[0];
    const float* cb = (const float*)d_in[1];
    if (n_in >= 2 && in_sizes[0] == QSTAGES * KCODES * DDIM &&
        in_sizes[1] == N_ROWS * DDIM) {
        x = (const float*)d_in[1];
        cb = (const float*)d_in[0];
    }

    cudaFuncSetAttribute(rvq_kernel, cudaFuncAttributeMaxDynamicSharedMemorySize,
                         SMEM_BYTES);

    hn_kernel<<<(QSTAGES * KCODES * 32 + 255) / 256, 256>>>(cb);

    const long long enc_n = (long long)N_ROWS * QSTAGES;
    const long long qz_n = (long long)N_ROWS * DDIM;

    float* qz = nullptr;
    float* enc_f = nullptr;
    int* enc_i = nullptr;
    if ((long long)out_size == enc_n + qz_n) {
        enc_f = (float*)d_out;
        qz = (float*)d_out + enc_n;
    } else if ((long long)out_size == qz_n) {
        qz = (float*)d_out;
    } else if ((long long)out_size == enc_n) {
        enc_i = (int*)d_out;
    } else {
        enc_f = (float*)d_out;
        if ((long long)out_size >= enc_n + qz_n) qz = (float*)d_out + enc_n;
    }

    rvq_kernel<<<N_ROWS / TM, NTHREADS, SMEM_BYTES>>>(x, cb, qz, enc_f, enc_i);
}

// round 5
// speedup vs baseline: 1.5440x; 1.5440x over previous
#include <cuda_runtime.h>
#include <cstdint>
#include <cstddef>

#define N_ROWS   262144
#define DDIM     64
#define QSTAGES  8
#define KCODES   1024
#define TM       256
#define TN       128
#define NTHREADS 512
#define RPAD     260            // rT/qT row stride (floats)
#define CPAD     132            // cbT row stride (floats)

// shared memory layout (float units)
#define OFF_RT   0
#define OFF_QT   (OFF_RT + DDIM * RPAD)          // 16640
#define OFF_CB   (OFF_QT + DDIM * RPAD)          // 33280 (double buffer)
#define OFF_HN   (OFF_CB + 2 * DDIM * CPAD)      // 50176
#define OFF_IDX  (OFF_HN + KCODES)               // 51200 (TM ints)
#define SMEM_FLOATS (OFF_IDX + TM)               // 51456
#define SMEM_BYTES  (SMEM_FLOATS * 4)            // 205824 B

// hn[q][k] = XLA-emulated fp32 sum(cb*cb) (warp-tree reduction)
__device__ float g_hn[QSTAGES * KCODES];

// ---------------- packed f32x2 helpers ----------------
__device__ __forceinline__ void ffma2(unsigned long long& acc,
                                      unsigned long long a,
                                      unsigned long long b) {
    asm("fma.rn.f32x2 %0, %1, %2, %0;" : "+l"(acc) : "l"(a), "l"(b));
}
__device__ __forceinline__ unsigned long long dup2(float v) {
    unsigned long long r;
    asm("mov.b64 %0, {%1, %1};" : "=l"(r) : "f"(v));
    return r;
}
__device__ __forceinline__ float2 unpack2(unsigned long long p) {
    float2 r;
    asm("mov.b64 {%0, %1}, %2;" : "=f"(r.x), "=f"(r.y) : "l"(p));
    return r;
}

// ---------------- codebook norms: emulate XLA row-reduction ----------------
__global__ void hn_kernel(const float* __restrict__ cb) {
    int warp = (blockIdx.x * blockDim.x + threadIdx.x) >> 5;
    int lane = threadIdx.x & 31;
    if (warp < QSTAGES * KCODES) {
        const float* row = cb + (size_t)warp * DDIM;
        float c0 = row[lane];
        float c1 = row[lane + 32];
        float acc = __fmaf_rn(c0, c0, 0.0f);
        acc = __fmaf_rn(c1, c1, acc);
#pragma unroll
        for (int off = 16; off > 0; off >>= 1) {
            float sh = __shfl_down_sync(0xffffffffu, acc, off);
            acc = acc + sh;
        }
        if (lane == 0) g_hn[warp] = acc;
    }
}

// ---- chunk staging: gmem -> transposed smem (conflict-free STS) ----
__device__ __forceinline__ void stage_chunk(const float* __restrict__ cbq,
                                            int c, float* __restrict__ buf,
                                            int tid) {
    int klocal = tid & 127;            // consecutive lanes -> consecutive cols
    int d0 = (tid >> 7) << 4;          // 0,16,32,48
    const float4* p = reinterpret_cast<const float4*>(
        cbq + ((size_t)(c * TN + klocal)) * DDIM + d0);
    float4 v0 = p[0], v1 = p[1], v2 = p[2], v3 = p[3];
    buf[(d0 +  0) * CPAD + klocal] = v0.x;
    buf[(d0 +  1) * CPAD + klocal] = v0.y;
    buf[(d0 +  2) * CPAD + klocal] = v0.z;
    buf[(d0 +  3) * CPAD + klocal] = v0.w;
    buf[(d0 +  4) * CPAD + klocal] = v1.x;
    buf[(d0 +  5) * CPAD + klocal] = v1.y;
    buf[(d0 +  6) * CPAD + klocal] = v1.z;
    buf[(d0 +  7) * CPAD + klocal] = v1.w;
    buf[(d0 +  8) * CPAD + klocal] = v2.x;
    buf[(d0 +  9) * CPAD + klocal] = v2.y;
    buf[(d0 + 10) * CPAD + klocal] = v2.z;
    buf[(d0 + 11) * CPAD + klocal] = v2.w;
    buf[(d0 + 12) * CPAD + klocal] = v3.x;
    buf[(d0 + 13) * CPAD + klocal] = v3.y;
    buf[(d0 + 14) * CPAD + klocal] = v3.z;
    buf[(d0 + 15) * CPAD + klocal] = v3.w;
}

// ---------------- main fused RVQ kernel ----------------
__global__ void __launch_bounds__(NTHREADS, 1)
rvq_kernel(const float* __restrict__ x, const float* __restrict__ cb,
           float* __restrict__ qz, float* __restrict__ enc_f,
           int* __restrict__ enc_i) {
    extern __shared__ float smem[];
    float* s_rT  = smem + OFF_RT;
    float* s_qT  = smem + OFF_QT;
    float* s_cbT = smem + OFF_CB;
    float* s_hn  = smem + OFF_HN;
    int*   s_idx = reinterpret_cast<int*>(smem + OFF_IDX);

    const int tid = threadIdx.x;
    const int tx = tid & 15;           // 16 col-groups
    const int ty = tid >> 4;           // 32 row-groups of 8
    const int row_base = blockIdx.x * TM;
    const int n2 = tid >> 1;           // update/init mapping: row
    const int dh = (tid & 1) << 5;     // and 32-d half

    // ---- init: rT = x (transposed), qT = 0 ----
    {
        const float4* xp = reinterpret_cast<const float4*>(
            x + (size_t)(row_base + n2) * DDIM + dh);
#pragma unroll
        for (int j = 0; j < 8; j++) {
            float4 v = xp[j];
            int dd = dh + (j << 2);
            s_rT[(dd + 0) * RPAD + n2] = v.x;
            s_rT[(dd + 1) * RPAD + n2] = v.y;
            s_rT[(dd + 2) * RPAD + n2] = v.z;
            s_rT[(dd + 3) * RPAD + n2] = v.w;
            s_qT[(dd + 0) * RPAD + n2] = 0.f;
            s_qT[(dd + 1) * RPAD + n2] = 0.f;
            s_qT[(dd + 2) * RPAD + n2] = 0.f;
            s_qT[(dd + 3) * RPAD + n2] = 0.f;
        }
    }

    for (int q = 0; q < QSTAGES; q++) {
        const float* cbq = cb + (size_t)q * (KCODES * DDIM);

#pragma unroll
        for (int i = 0; i < KCODES / NTHREADS; i++)
            s_hn[tid + i * NTHREADS] = g_hn[q * KCODES + tid + i * NTHREADS];
        __syncthreads();

        stage_chunk(cbq, 0, s_cbT, tid);
        __syncthreads();

        float bestd[8];
        int besti[8];
#pragma unroll
        for (int i = 0; i < 8; i++) { bestd[i] = 3.0e38f; besti[i] = 0x7fffffff; }

        for (int c = 0; c < KCODES / TN; c++) {
            const float* bufb = s_cbT + (c & 1) * (DDIM * CPAD);

            unsigned long long acc[8][4];
#pragma unroll
            for (int i = 0; i < 8; i++)
#pragma unroll
                for (int j = 0; j < 4; j++) acc[i][j] = 0ULL;

            // s = sum_d r[d]*c[d]: fma, d ascending, single accumulator per
            // output (per packed half) — bit-identical to SGEMM's k-loop.
#pragma unroll 4
            for (int d = 0; d < DDIM; d++) {
                const float* rrow = s_rT + d * RPAD + (ty << 3);
                float4 a0 = *reinterpret_cast<const float4*>(rrow);
                float4 a1 = *reinterpret_cast<const float4*>(rrow + 4);
                const float* brow = bufb + d * CPAD + (tx << 2);
                ulonglong2 b0 = *reinterpret_cast<const ulonglong2*>(brow);
                ulonglong2 b1 = *reinterpret_cast<const ulonglong2*>(brow + 64);
                float av[8] = {a0.x, a0.y, a0.z, a0.w, a1.x, a1.y, a1.z, a1.w};
#pragma unroll
                for (int i = 0; i < 8; i++) {
                    unsigned long long ad = dup2(av[i]);
                    ffma2(acc[i][0], ad, b0.x);
                    ffma2(acc[i][1], ad, b0.y);
                    ffma2(acc[i][2], ad, b1.x);
                    ffma2(acc[i][3], ad, b1.y);
                }
            }

            // epilogue: d = fma(-2, s, hn); running strict min (cols ascending)
            {
                int cb1 = c * TN + (tx << 2);
                float4 h0 = *reinterpret_cast<const float4*>(s_hn + cb1);
                float4 h1 = *reinterpret_cast<const float4*>(s_hn + cb1 + 64);
                float hh[8] = {h0.x, h0.y, h0.z, h0.w, h1.x, h1.y, h1.z, h1.w};
#pragma unroll
                for (int i = 0; i < 8; i++) {
#pragma unroll
                    for (int j = 0; j < 4; j++) {
                        float2 v = unpack2(acc[i][j]);
                        int c0 = cb1 + ((j >> 1) ? 64 : 0) + ((j & 1) << 1);
                        float d0v = __fmaf_rn(-2.0f, v.x, hh[(j >> 1) * 4 + ((j & 1) << 1)]);
                        float d1v = __fmaf_rn(-2.0f, v.y, hh[(j >> 1) * 4 + ((j & 1) << 1) + 1]);
                        if (d0v < bestd[i]) { bestd[i] = d0v; besti[i] = c0; }
                        if (d1v < bestd[i]) { bestd[i] = d1v; besti[i] = c0 + 1; }
                    }
                }
            }

            if (c < KCODES / TN - 1) {
                stage_chunk(cbq, c + 1, s_cbT + ((c + 1) & 1) * (DDIM * CPAD), tid);
                __syncthreads();
            }
        }

        // cross-lane argmin merge over 16 tx lanes (lexicographic)
#pragma unroll
        for (int i = 0; i < 8; i++) {
#pragma unroll
            for (int off = 8; off > 0; off >>= 1) {
                float ov = __shfl_xor_sync(0xffffffffu, bestd[i], off);
                int oi = __shfl_xor_sync(0xffffffffu, besti[i], off);
                if (ov < bestd[i] || (ov == bestd[i] && oi < besti[i])) {
                    bestd[i] = ov;
                    besti[i] = oi;
                }
            }
        }
        if (tx == 0) {
#pragma unroll
            for (int i = 0; i < 8; i++) {
                int row = (ty << 3) + i;
                int id = besti[i];
                s_idx[row] = id;
                size_t e = (size_t)(row_base + row) * QSTAGES + q;
                if (enc_f) enc_f[e] = (float)id;
                if (enc_i) enc_i[e] = id;
            }
        }
        __syncthreads();

        // ---- update: q += cb[idx] (fp32, ref order); r = x - q ----
        {
            int id = s_idx[n2];
            const float4* cp = reinterpret_cast<const float4*>(
                cbq + (size_t)id * DDIM + dh);
            const float4* xp = reinterpret_cast<const float4*>(
                x + (size_t)(row_base + n2) * DDIM + dh);
#pragma unroll
            for (int j = 0; j < 8; j++) {
                float4 cv = cp[j];
                float4 xv = xp[j];
                int dd = dh + (j << 2);
                float q0 = s_qT[(dd + 0) * RPAD + n2] + cv.x;
                float q1 = s_qT[(dd + 1) * RPAD + n2] + cv.y;
                float q2 = s_qT[(dd + 2) * RPAD + n2] + cv.z;
                float q3 = s_qT[(dd + 3) * RPAD + n2] + cv.w;
                s_qT[(dd + 0) * RPAD + n2] = q0;
                s_qT[(dd + 1) * RPAD + n2] = q1;
                s_qT[(dd + 2) * RPAD + n2] = q2;
                s_qT[(dd + 3) * RPAD + n2] = q3;
                s_rT[(dd + 0) * RPAD + n2] = xv.x - q0;
                s_rT[(dd + 1) * RPAD + n2] = xv.y - q1;
                s_rT[(dd + 2) * RPAD + n2] = xv.z - q2;
                s_rT[(dd + 3) * RPAD + n2] = xv.w - q3;
            }
        }
        __syncthreads();
    }

    // ---- output quantized = qT (bit-exact accumulation) ----
    if (qz) {
        size_t base = (size_t)(row_base + n2) * DDIM + dh;
#pragma unroll
        for (int j = 0; j < 8; j++) {
            int dd = dh + (j << 2);
            float4 o;
            o.x = s_qT[(dd + 0) * RPAD + n2];
            o.y = s_qT[(dd + 1) * RPAD + n2];
            o.z = s_qT[(dd + 2) * RPAD + n2];
            o.w = s_qT[(dd + 3) * RPAD + n2];
            *reinterpret_cast<float4*>(qz + base + (j << 2)) = o;
        }
    }
}

// ---------------- launch ----------------
extern "C" void kernel_launch(void* const* d_in, const int* in_sizes, int n_in,
                              void* d_out, int out_size) {
    const float* x = (const float*)d_in[0];
    const float* cb = (const float*)d_in[1];
    if (n_in >= 2 && in_sizes[0] == QSTAGES * KCODES * DDIM &&
        in_sizes[1] == N_ROWS * DDIM) {
        x = (const float*)d_in[1];
        cb = (const float*)d_in[0];
    }

    cudaFuncSetAttribute(rvq_kernel, cudaFuncAttributeMaxDynamicSharedMemorySize,
                         SMEM_BYTES);

    hn_kernel<<<(QSTAGES * KCODES * 32 + 255) / 256, 256>>>(cb);

    const long long enc_n = (long long)N_ROWS * QSTAGES;
    const long long qz_n = (long long)N_ROWS * DDIM;

    float* qz = nullptr;
    float* enc_f = nullptr;
    int* enc_i = nullptr;
    if ((long long)out_size == enc_n + qz_n) {
        enc_f = (float*)d_out;
        qz = (float*)d_out + enc_n;
    } else if ((long long)out_size == qz_n) {
        qz = (float*)d_out;
    } else if ((long long)out_size == enc_n) {
        enc_i = (int*)d_out;
    } else {
        enc_f = (float*)d_out;
        if ((long long)out_size >= enc_n + qz_n) qz = (float*)d_out + enc_n;
    }

    rvq_kernel<<<N_ROWS / TM, NTHREADS, SMEM_BYTES>>>(x, cb, qz, enc_f, enc_i);
}

// round 6
// speedup vs baseline: 1.5449x; 1.0006x over previous
#include <cuda_runtime.h>
#include <cstdint>
#include <cstddef>

#define N_ROWS   262144
#define DDIM     64
#define QSTAGES  8
#define KCODES   1024
#define TM       256
#define TN       128
#define NTHREADS 512
#define RPAD     260            // rT/qT row stride (floats)
#define CPAD     132            // cbT row stride (floats)

// shared memory layout (float units)
#define OFF_RT   0
#define OFF_QT   (OFF_RT + DDIM * RPAD)          // 16640
#define OFF_CB   (OFF_QT + DDIM * RPAD)          // 33280 (double buffer)
#define OFF_HN   (OFF_CB + 2 * DDIM * CPAD)      // 50176
#define OFF_IDX  (OFF_HN + KCODES)               // 51200 (TM ints)
#define SMEM_FLOATS (OFF_IDX + TM)               // 51456
#define SMEM_BYTES  (SMEM_FLOATS * 4)            // 205824 B

// hn[q][k] = XLA-emulated fp32 sum(cb*cb) (warp-tree reduction)
__device__ float g_hn[QSTAGES * KCODES];

// ---------------- packed f32x2 helpers ----------------
__device__ __forceinline__ void ffma2(unsigned long long& acc,
                                      unsigned long long a,
                                      unsigned long long b) {
    asm("fma.rn.f32x2 %0, %1, %2, %0;" : "+l"(acc) : "l"(a), "l"(b));
}
__device__ __forceinline__ unsigned long long dup2(float v) {
    unsigned long long r;
    asm("mov.b64 %0, {%1, %1};" : "=l"(r) : "f"(v));
    return r;
}
__device__ __forceinline__ float2 unpack2(unsigned long long p) {
    float2 r;
    asm("mov.b64 {%0, %1}, %2;" : "=f"(r.x), "=f"(r.y) : "l"(p));
    return r;
}

// ---------------- codebook norms: emulate XLA row-reduction ----------------
__global__ void hn_kernel(const float* __restrict__ cb) {
    int warp = (blockIdx.x * blockDim.x + threadIdx.x) >> 5;
    int lane = threadIdx.x & 31;
    if (warp < QSTAGES * KCODES) {
        const float* row = cb + (size_t)warp * DDIM;
        float c0 = row[lane];
        float c1 = row[lane + 32];
        float acc = __fmaf_rn(c0, c0, 0.0f);
        acc = __fmaf_rn(c1, c1, acc);
#pragma unroll
        for (int off = 16; off > 0; off >>= 1) {
            float sh = __shfl_down_sync(0xffffffffu, acc, off);
            acc = acc + sh;
        }
        if (lane == 0) g_hn[warp] = acc;
    }
}

// ---- chunk staging: gmem -> transposed smem (conflict-free STS) ----
__device__ __forceinline__ void stage_chunk(const float* __restrict__ cbq,
                                            int c, float* __restrict__ buf,
                                            int tid) {
    int klocal = tid & 127;            // consecutive lanes -> consecutive cols
    int d0 = (tid >> 7) << 4;          // 0,16,32,48
    const float4* p = reinterpret_cast<const float4*>(
        cbq + ((size_t)(c * TN + klocal)) * DDIM + d0);
    float4 v0 = p[0], v1 = p[1], v2 = p[2], v3 = p[3];
    buf[(d0 +  0) * CPAD + klocal] = v0.x;
    buf[(d0 +  1) * CPAD + klocal] = v0.y;
    buf[(d0 +  2) * CPAD + klocal] = v0.z;
    buf[(d0 +  3) * CPAD + klocal] = v0.w;
    buf[(d0 +  4) * CPAD + klocal] = v1.x;
    buf[(d0 +  5) * CPAD + klocal] = v1.y;
    buf[(d0 +  6) * CPAD + klocal] = v1.z;
    buf[(d0 +  7) * CPAD + klocal] = v1.w;
    buf[(d0 +  8) * CPAD + klocal] = v2.x;
    buf[(d0 +  9) * CPAD + klocal] = v2.y;
    buf[(d0 + 10) * CPAD + klocal] = v2.z;
    buf[(d0 + 11) * CPAD + klocal] = v2.w;
    buf[(d0 + 12) * CPAD + klocal] = v3.x;
    buf[(d0 + 13) * CPAD + klocal] = v3.y;
    buf[(d0 + 14) * CPAD + klocal] = v3.z;
    buf[(d0 + 15) * CPAD + klocal] = v3.w;
}

// ---------------- main fused RVQ kernel ----------------
__global__ void __launch_bounds__(NTHREADS, 1)
rvq_kernel(const float* __restrict__ x, const float* __restrict__ cb,
           float* __restrict__ qz, float* __restrict__ enc_f,
           int* __restrict__ enc_i) {
    extern __shared__ float smem[];
    float* s_rT  = smem + OFF_RT;
    float* s_qT  = smem + OFF_QT;
    float* s_cbT = smem + OFF_CB;
    float* s_hn  = smem + OFF_HN;
    int*   s_idx = reinterpret_cast<int*>(smem + OFF_IDX);

    const int tid = threadIdx.x;
    const int tx = tid & 15;           // 16 col-groups
    const int ty = tid >> 4;           // 32 row-groups of 8
    const int row_base = blockIdx.x * TM;
    const int n2 = tid >> 1;           // update/init mapping: row
    const int dh = (tid & 1) << 5;     // and 32-d half

    // ---- init: rT = x (transposed), qT = 0 ----
    {
        const float4* xp = reinterpret_cast<const float4*>(
            x + (size_t)(row_base + n2) * DDIM + dh);
#pragma unroll
        for (int j = 0; j < 8; j++) {
            float4 v = xp[j];
            int dd = dh + (j << 2);
            s_rT[(dd + 0) * RPAD + n2] = v.x;
            s_rT[(dd + 1) * RPAD + n2] = v.y;
            s_rT[(dd + 2) * RPAD + n2] = v.z;
            s_rT[(dd + 3) * RPAD + n2] = v.w;
            s_qT[(dd + 0) * RPAD + n2] = 0.f;
            s_qT[(dd + 1) * RPAD + n2] = 0.f;
            s_qT[(dd + 2) * RPAD + n2] = 0.f;
            s_qT[(dd + 3) * RPAD + n2] = 0.f;
        }
    }

    for (int q = 0; q < QSTAGES; q++) {
        const float* cbq = cb + (size_t)q * (KCODES * DDIM);

#pragma unroll
        for (int i = 0; i < KCODES / NTHREADS; i++)
            s_hn[tid + i * NTHREADS] = g_hn[q * KCODES + tid + i * NTHREADS];
        __syncthreads();

        stage_chunk(cbq, 0, s_cbT, tid);
        __syncthreads();

        float bestd[8];
        int besti[8];
#pragma unroll
        for (int i = 0; i < 8; i++) { bestd[i] = 3.0e38f; besti[i] = 0x7fffffff; }

        for (int c = 0; c < KCODES / TN; c++) {
            const float* bufb = s_cbT + (c & 1) * (DDIM * CPAD);

            unsigned long long acc[8][4];
#pragma unroll
            for (int i = 0; i < 8; i++)
#pragma unroll
                for (int j = 0; j < 4; j++) acc[i][j] = 0ULL;

            // s = sum_d r[d]*c[d]: fma, d ascending, single accumulator per
            // output (per packed half) — bit-identical to SGEMM's k-loop.
#pragma unroll 4
            for (int d = 0; d < DDIM; d++) {
                const float* rrow = s_rT + d * RPAD + (ty << 3);
                float4 a0 = *reinterpret_cast<const float4*>(rrow);
                float4 a1 = *reinterpret_cast<const float4*>(rrow + 4);
                const float* brow = bufb + d * CPAD + (tx << 2);
                ulonglong2 b0 = *reinterpret_cast<const ulonglong2*>(brow);
                ulonglong2 b1 = *reinterpret_cast<const ulonglong2*>(brow + 64);
                float av[8] = {a0.x, a0.y, a0.z, a0.w, a1.x, a1.y, a1.z, a1.w};
#pragma unroll
                for (int i = 0; i < 8; i++) {
                    unsigned long long ad = dup2(av[i]);
                    ffma2(acc[i][0], ad, b0.x);
                    ffma2(acc[i][1], ad, b0.y);
                    ffma2(acc[i][2], ad, b1.x);
                    ffma2(acc[i][3], ad, b1.y);
                }
            }

            // epilogue: d = fma(-2, s, hn); running strict min (cols ascending)
            {
                int cb1 = c * TN + (tx << 2);
                float4 h0 = *reinterpret_cast<const float4*>(s_hn + cb1);
                float4 h1 = *reinterpret_cast<const float4*>(s_hn + cb1 + 64);
                float hh[8] = {h0.x, h0.y, h0.z, h0.w, h1.x, h1.y, h1.z, h1.w};
#pragma unroll
                for (int i = 0; i < 8; i++) {
#pragma unroll
                    for (int j = 0; j < 4; j++) {
                        float2 v = unpack2(acc[i][j]);
                        int c0 = cb1 + ((j >> 1) ? 64 : 0) + ((j & 1) << 1);
                        float d0v = __fmaf_rn(-2.0f, v.x, hh[(j >> 1) * 4 + ((j & 1) << 1)]);
                        float d1v = __fmaf_rn(-2.0f, v.y, hh[(j >> 1) * 4 + ((j & 1) << 1) + 1]);
                        if (d0v < bestd[i]) { bestd[i] = d0v; besti[i] = c0; }
                        if (d1v < bestd[i]) { bestd[i] = d1v; besti[i] = c0 + 1; }
                    }
                }
            }

            if (c < KCODES / TN - 1) {
                stage_chunk(cbq, c + 1, s_cbT + ((c + 1) & 1) * (DDIM * CPAD), tid);
                __syncthreads();
            }
        }

        // cross-lane argmin merge over 16 tx lanes (lexicographic)
#pragma unroll
        for (int i = 0; i < 8; i++) {
#pragma unroll
            for (int off = 8; off > 0; off >>= 1) {
                float ov = __shfl_xor_sync(0xffffffffu, bestd[i], off);
                int oi = __shfl_xor_sync(0xffffffffu, besti[i], off);
                if (ov < bestd[i] || (ov == bestd[i] && oi < besti[i])) {
                    bestd[i] = ov;
                    besti[i] = oi;
                }
            }
        }
        if (tx == 0) {
#pragma unroll
            for (int i = 0; i < 8; i++) {
                int row = (ty << 3) + i;
                int id = besti[i];
                s_idx[row] = id;
                size_t e = (size_t)(row_base + row) * QSTAGES + q;
                if (enc_f) enc_f[e] = (float)id;
                if (enc_i) enc_i[e] = id;
            }
        }
        __syncthreads();

        // ---- update: q += cb[idx] (fp32, ref order); r = x - q ----
        {
            int id = s_idx[n2];
            const float4* cp = reinterpret_cast<const float4*>(
                cbq + (size_t)id * DDIM + dh);
            const float4* xp = reinterpret_cast<const float4*>(
                x + (size_t)(row_base + n2) * DDIM + dh);
#pragma unroll
            for (int j = 0; j < 8; j++) {
                float4 cv = cp[j];
                float4 xv = xp[j];
                int dd = dh + (j << 2);
                float q0 = s_qT[(dd + 0) * RPAD + n2] + cv.x;
                float q1 = s_qT[(dd + 1) * RPAD + n2] + cv.y;
                float q2 = s_qT[(dd + 2) * RPAD + n2] + cv.z;
                float q3 = s_qT[(dd + 3) * RPAD + n2] + cv.w;
                s_qT[(dd + 0) * RPAD + n2] = q0;
                s_qT[(dd + 1) * RPAD + n2] = q1;
                s_qT[(dd + 2) * RPAD + n2] = q2;
                s_qT[(dd + 3) * RPAD + n2] = q3;
                s_rT[(dd + 0) * RPAD + n2] = xv.x - q0;
                s_rT[(dd + 1) * RPAD + n2] = xv.y - q1;
                s_rT[(dd + 2) * RPAD + n2] = xv.z - q2;
                s_rT[(dd + 3) * RPAD + n2] = xv.w - q3;
            }
        }
        __syncthreads();
    }

    // ---- output quantized = qT (bit-exact accumulation) ----
    if (qz) {
        size_t base = (size_t)(row_base + n2) * DDIM + dh;
#pragma unroll
        for (int j = 0; j < 8; j++) {
            int dd = dh + (j << 2);
            float4 o;
            o.x = s_qT[(dd + 0) * RPAD + n2];
            o.y = s_qT[(dd + 1) * RPAD + n2];
            o.z = s_qT[(dd + 2) * RPAD + n2];
            o.w = s_qT[(dd + 3) * RPAD + n2];
            *reinterpret_cast<float4*>(qz + base + (j << 2)) = o;
        }
    }
}

// ---------------- launch ----------------
extern "C" void kernel_launch(void* const* d_in, const int* in_sizes, int n_in,
                              void* d_out, int out_size) {
    const float* x = (const float*)d_in[0];
    const float* cb = (const float*)d_in[1];
    if (n_in >= 2 && in_sizes[0] == QSTAGES * KCODES * DDIM &&
        in_sizes[1] == N_ROWS * DDIM) {
        x = (const float*)d_in[1];
        cb = (const float*)d_in[0];
    }

    cudaFuncSetAttribute(rvq_kernel, cudaFuncAttributeMaxDynamicSharedMemorySize,
                         SMEM_BYTES);

    hn_kernel<<<(QSTAGES * KCODES * 32 + 255) / 256, 256>>>(cb);

    const long long enc_n = (long long)N_ROWS * QSTAGES;
    const long long qz_n = (long long)N_ROWS * DDIM;

    float* qz = nullptr;
    float* enc_f = nullptr;
    int* enc_i = nullptr;
    if ((long long)out_size == enc_n + qz_n) {
        enc_f = (float*)d_out;
        qz = (float*)d_out + enc_n;
    } else if ((long long)out_size == qz_n) {
        qz = (float*)d_out;
    } else if ((long long)out_size == enc_n) {
        enc_i = (int*)d_out;
    } else {
        enc_f = (float*)d_out;
        if ((long long)out_size >= enc_n + qz_n) qz = (float*)d_out + enc_n;
    }

    rvq_kernel<<<N_ROWS / TM, NTHREADS, SMEM_BYTES>>>(x, cb, qz, enc_f, enc_i);
}